// round 14
// baseline (speedup 1.0000x reference)
#include <cuda_runtime.h>
#include <cuda_fp16.h>
#include <cstdint>
#include <math.h>

#define BB    8
#define CIN   256
#define COUT  256
#define NP    8192
#define KT    9
#define DILT  6
#define PADT  24
#define NCHUNK 36          // (KT * CIN) / 64

// ---------------- device scratch ----------------
__device__ float   g_gw[BB * KT * NP];              // gate weights [b][k][n]
// A fragments in MMA register order: [otile 2][chunk 36][wm 4][it 8][lane 32] x uint4
// it = ks*2 + mt; uint4 = {a0,a1,a2,a3} for that (mt,ks):
//   a0=(r,k0|k0+1) a1=(r+8,k0|k0+1) a2=(r,k0+8|k0+9) a3=(r+8,k0+8|k0+9)
//   r = wm*32 + mt*16 + lane/4,  k0 = ks*16 + (lane%4)*2
__device__ uint4   g_Afrag[2 * NCHUNK * 4 * 8 * 32];
__device__ float   g_sum[COUT];
__device__ float   g_sumsq[COUT];
__device__ float   g_scale[COUT];
__device__ float   g_shift[COUT];

// ---------------- helpers ----------------
__device__ __forceinline__ uint32_t smem_u32(const void* p) {
    uint32_t a;
    asm("{ .reg .u64 t; cvta.to.shared.u64 t, %1; cvt.u32.u64 %0, t; }" : "=r"(a) : "l"(p));
    return a;
}
__device__ __forceinline__ void ldsm_x4t(uint32_t* r, uint32_t addr) {
    asm volatile("ldmatrix.sync.aligned.m8n8.x4.trans.shared.b16 {%0,%1,%2,%3}, [%4];"
        : "=r"(r[0]), "=r"(r[1]), "=r"(r[2]), "=r"(r[3]) : "r"(addr));
}
__device__ __forceinline__ void mma16816(float* c, const uint32_t* a, uint32_t b0, uint32_t b1) {
    asm volatile(
        "mma.sync.aligned.m16n8k16.row.col.f32.f16.f16.f32 "
        "{%0,%1,%2,%3}, {%4,%5,%6,%7}, {%8,%9}, {%0,%1,%2,%3};"
        : "+f"(c[0]), "+f"(c[1]), "+f"(c[2]), "+f"(c[3])
        : "r"(a[0]), "r"(a[1]), "r"(a[2]), "r"(a[3]), "r"(b0), "r"(b1));
}

// ---------------- kernel 0 ----------------
__global__ void zero_sums_kernel() {
    int t = threadIdx.x;
    g_sum[t] = 0.f;
    g_sumsq[t] = 0.f;
}

// ---------------- kernel 1: tap gate weights ----------------
__global__ void gweight_kernel(const float* __restrict__ coords,
                               const float* __restrict__ rot,
                               const float* __restrict__ dist) {
    int n = blockIdx.x * blockDim.x + threadIdx.x;
    int b = blockIdx.y;
    const float* cb = coords + (size_t)b * 3 * NP;
    const float* rb = rot    + (size_t)b * 3 * NP;

    float c0x = cb[n], c0y = cb[NP + n], c0z = cb[2 * NP + n];
    float r0x = rb[n], r0y = rb[NP + n], r0z = rb[2 * NP + n];
    float d0  = dist[(size_t)b * NP + n];
    float r0sq = r0x * r0x + r0y * r0y + r0z * r0z;

#pragma unroll
    for (int k = 0; k < KT; k++) {
        int j = n + k * DILT - PADT;
        float cjx = 0.f, cjy = 0.f, cjz = 0.f;
        float rjx = 0.f, rjy = 0.f, rjz = 0.f;
        float dj  = 0.f;
        if (j >= 0 && j < NP) {
            cjx = cb[j]; cjy = cb[NP + j]; cjz = cb[2 * NP + j];
            rjx = rb[j]; rjy = rb[NP + j]; rjz = rb[2 * NP + j];
            dj  = dist[(size_t)b * NP + j];
        }
        float dx = c0x - cjx, dy = c0y - cjy, dz = c0z - cjz;
        float dc = dx * dx + dy * dy + dz * dz;
        float dd = (d0 - dj) * (d0 - dj);
        float g  = expf(-0.5f * (dc + dd));
        float num  = r0x * rjx + r0y * rjy + r0z * rjz;
        float rjsq = rjx * rjx + rjy * rjy + rjz * rjz;
        float den  = sqrtf(r0sq * rjsq) + 1e-8f;
        g_gw[((size_t)b * KT + k) * NP + n] = g * fabsf(num / den);
    }
}

// ---------------- kernel 2: pack W into MMA A-fragments ----------------
__global__ void wfrag_kernel(const float* __restrict__ W) {
    int idx = blockIdx.x * 256 + threadIdx.x;       // 0 .. 73727
    if (idx >= 2 * NCHUNK * 4 * 8 * 32) return;
    int lane  = idx & 31;
    int it    = (idx >> 5) & 7;
    int wm    = (idx >> 8) & 3;
    int chunk = (idx >> 10) % NCHUNK;
    int otile = (idx >> 10) / NCHUNK;
    int ks = it >> 1, mt = it & 1;
    int r  = wm * 32 + mt * 16 + (lane >> 2);
    int k0 = ks * 16 + (lane & 3) * 2;
    int ktap  = chunk >> 2;
    int cbase = (chunk & 3) << 6;
    int o = otile * 128 + r;

    // gather 8 W values -> 4 packed fp16x2 regs
    auto wv = [&](int row, int kc) -> __half {
        return __float2half(W[((size_t)(otile * 128 + row) * CIN + cbase + kc) * KT + ktap]);
    };
    __half2 a0 = __halves2half2(wv(r,     k0),     wv(r,     k0 + 1));
    __half2 a1 = __halves2half2(wv(r + 8, k0),     wv(r + 8, k0 + 1));
    __half2 a2 = __halves2half2(wv(r,     k0 + 8), wv(r,     k0 + 9));
    __half2 a3 = __halves2half2(wv(r + 8, k0 + 8), wv(r + 8, k0 + 9));
    uint4 v;
    v.x = *(uint32_t*)&a0;  v.y = *(uint32_t*)&a1;
    v.z = *(uint32_t*)&a2;  v.w = *(uint32_t*)&a3;
    g_Afrag[idx] = v;
}

// ---------------- SMEM layout ----------------
#define OFF_B   0          // 2 bufs x 16KB fp16 gated x = 32768
#define OFF_ST  32768      // stats: 256 floats
#define SMEM_TOTAL 33792

// ---- load half (4 row-groups) of raw x for chunk s into 4 float4 regs ----
__device__ __forceinline__ void loadVh(float4* vr,
                                       const float* __restrict__ xb,
                                       int n_base, int s, int tid, int h) {
    const int off = (s >> 2) * DILT - PADT;
    const int c0  = (s & 3) << 6;
    const int nn  = (tid & 31) << 2;
    const int r0h = (tid >> 5) + h * 32;
    const int src = n_base + off + nn;
    const float* gs = xb + (size_t)(c0 + r0h) * NP + src;

    if (src >= 0 && src + 3 < NP) {              // interior
        if ((off & 3) == 0) {                    // 16B-aligned tap (even k)
#pragma unroll
            for (int it = 0; it < 4; it++)
                vr[it] = *(const float4*)(gs + (size_t)it * 8 * NP);
        } else {                                 // 8B-aligned tap (odd k)
#pragma unroll
            for (int it = 0; it < 4; it++) {
                const float* gp = gs + (size_t)it * 8 * NP;
                float2 p0 = *(const float2*)gp;
                float2 p1 = *(const float2*)(gp + 2);
                vr[it] = make_float4(p0.x, p0.y, p1.x, p1.y);
            }
        }
    } else if (src + 3 < 0 || src >= NP) {       // fully OOB
#pragma unroll
        for (int it = 0; it < 4; it++)
            vr[it] = make_float4(0.f, 0.f, 0.f, 0.f);
    } else {                                     // straddle (rare edge)
#pragma unroll
        for (int it = 0; it < 4; it++) {
            const float* gp = gs + (size_t)it * 8 * NP;
            float e0 = (src + 0 >= 0 && src + 0 < NP) ? gp[0] : 0.f;
            float e1 = (src + 1 >= 0 && src + 1 < NP) ? gp[1] : 0.f;
            float e2 = (src + 2 >= 0 && src + 2 < NP) ? gp[2] : 0.f;
            float e3 = (src + 3 >= 0 && src + 3 < NP) ? gp[3] : 0.f;
            vr[it] = make_float4(e0, e1, e2, e3);
        }
    }
}

// ---- gate + fp16 + STS half into B tile ([kc 64][n 128], 256B swizzled rows) ----
// bofs is a BYTE OFFSET from smem base.
__device__ __forceinline__ void convertBh(char* smem, uint32_t bofs, const float4* vr,
                                          int b, int n_base, int s, int tid, int h) {
    const int kk  = s >> 2;
    const int nn  = (tid & 31) << 2;
    const int r0h = (tid >> 5) + h * 32;
    const float4 g4 = *(const float4*)(g_gw + ((size_t)b * KT + kk) * NP + n_base + nn);
#pragma unroll
    for (int it = 0; it < 4; it++) {
        int row = r0h + it * 8;
        float4 v = vr[it];
        __half2 h01 = __floats2half2_rn(v.x * g4.x, v.y * g4.y);
        __half2 h23 = __floats2half2_rn(v.z * g4.z, v.w * g4.w);
        uint32_t ofs = (uint32_t)(row * 256) + (((uint32_t)(nn * 2)) ^ ((uint32_t)(row & 7) << 4));
        *(uint2*)(smem + bofs + ofs) = make_uint2(*(uint32_t*)&h01, *(uint32_t*)&h23);
    }
}

// ---------------- kernel 3: HMMA fused gated dilated conv ----------------
__global__ void __launch_bounds__(256, 2) conv12_kernel(
    const float* __restrict__ x,
    const float* __restrict__ bias,
    float* __restrict__ out) {

    extern __shared__ __align__(16) char smem[];
    const uint32_t sbase = smem_u32(smem);

    const int tid  = threadIdx.x;
    const int lane = tid & 31;
    const int wid  = tid >> 5;
    const int wm = wid & 3;
    const int wn = wid >> 2;
    const int g  = lane >> 2;
    const int tg = lane & 3;

    const int b      = blockIdx.z;
    const int n_base = blockIdx.x * 128;
    const int otile  = blockIdx.y;
    const int o_base = otile * 128;

    const float* xb = x + (size_t)b * CIN * NP;
    // per-warp A fragment base (uint4 units): [otile][chunk][wm][it][lane]
    const uint4* Afw = g_Afrag + (((size_t)otile * NCHUNK * 4 + wm) * 8) * 32 + lane;

    const int b_nbyte = wn * 128 + ((lane >> 4) << 4);
    const int b_kcl   = lane & 15;

    float acc[2][8][4];
#pragma unroll
    for (int mt = 0; mt < 2; mt++)
#pragma unroll
        for (int nt = 0; nt < 8; nt++)
#pragma unroll
            for (int r = 0; r < 4; r++) acc[mt][nt][r] = 0.f;

    float4 vr[4];

    // ---- prologue: stage B[0] ----
    {
        loadVh(vr, xb, n_base, 0, tid, 0);
        convertBh(smem, OFF_B, vr, b, n_base, 0, tid, 0);
        loadVh(vr, xb, n_base, 0, tid, 1);
        convertBh(smem, OFF_B, vr, b, n_base, 0, tid, 1);
        __syncthreads();
    }

    // ---- mainloop: one sync per chunk; A fragments direct from global ----
    for (int i = 0; i < NCHUNK; i++) {
        const int  cur = i & 1;
        const bool hn  = (i + 1 < NCHUNK);
        const uint32_t Bb    = sbase + OFF_B + cur * 16384;
        const uint32_t BnOfs = OFF_B + (cur ^ 1) * 16384;
        const uint4* Afc = Afw + (size_t)i * 4 * 8 * 32;   // this chunk, this wm

        // A fragments for ks 0,1 (it 0..3)
        uint4 a4[4];
#pragma unroll
        for (int q = 0; q < 4; q++) a4[q] = Afc[q * 32];

        if (hn) loadVh(vr, xb, n_base, i + 1, tid, 0);

        // compute ks = 0, 1
#pragma unroll
        for (int ks = 0; ks < 2; ks++) {
            const int kc = ks * 16 + b_kcl;
            const uint32_t kb = (uint32_t)kc * 256;
            const uint32_t xm = ((uint32_t)kc & 7) << 4;
#pragma unroll
            for (int nt2 = 0; nt2 < 4; nt2++) {
                uint32_t br[4];
                const uint32_t nb = (uint32_t)(b_nbyte + nt2 * 32);
                ldsm_x4t(br, Bb + kb + (nb ^ xm));
#pragma unroll
                for (int mt = 0; mt < 2; mt++) {
                    const uint32_t* ah = (const uint32_t*)&a4[ks * 2 + mt];
                    mma16816(acc[mt][nt2 * 2 + 0], ah, br[0], br[1]);
                    mma16816(acc[mt][nt2 * 2 + 1], ah, br[2], br[3]);
                }
            }
        }

        // A fragments for ks 2,3 (it 4..7)
#pragma unroll
        for (int q = 0; q < 4; q++) a4[q] = Afc[(4 + q) * 32];

        if (hn) {
            convertBh(smem, BnOfs, vr, b, n_base, i + 1, tid, 0);   // B[nxt] half0
            loadVh(vr, xb, n_base, i + 1, tid, 1);
        }

        // compute ks = 2, 3
#pragma unroll
        for (int ks = 0; ks < 2; ks++) {
            const int kc = (ks + 2) * 16 + b_kcl;
            const uint32_t kb = (uint32_t)kc * 256;
            const uint32_t xm = ((uint32_t)kc & 7) << 4;
#pragma unroll
            for (int nt2 = 0; nt2 < 4; nt2++) {
                uint32_t br[4];
                const uint32_t nb = (uint32_t)(b_nbyte + nt2 * 32);
                ldsm_x4t(br, Bb + kb + (nb ^ xm));
#pragma unroll
                for (int mt = 0; mt < 2; mt++) {
                    const uint32_t* ah = (const uint32_t*)&a4[ks * 2 + mt];
                    mma16816(acc[mt][nt2 * 2 + 0], ah, br[0], br[1]);
                    mma16816(acc[mt][nt2 * 2 + 1], ah, br[2], br[3]);
                }
            }
        }

        if (hn) convertBh(smem, BnOfs, vr, b, n_base, i + 1, tid, 1);  // B[nxt] half1

        __syncthreads();    // B[nxt] ready; B[cur] readers done
    }

    // ---- epilogue ----
    float* bst = (float*)(smem + OFF_ST);
    bst[tid] = 0.f;
    __syncthreads();

    float s4[4] = {0.f, 0.f, 0.f, 0.f}, q4[4] = {0.f, 0.f, 0.f, 0.f};
#pragma unroll
    for (int mt = 0; mt < 2; mt++) {
        const int r0v = wm * 32 + mt * 16 + g;
        const int r1v = r0v + 8;
        const float b0v = bias[o_base + r0v];
        const float b1v = bias[o_base + r1v];
        float* p0 = out + ((size_t)b * COUT + o_base + r0v) * NP + n_base + wn * 64 + 2 * tg;
        float* p1 = out + ((size_t)b * COUT + o_base + r1v) * NP + n_base + wn * 64 + 2 * tg;
#pragma unroll
        for (int nt = 0; nt < 8; nt++) {
            float v0 = acc[mt][nt][0] + b0v;
            float v1 = acc[mt][nt][1] + b0v;
            float v2 = acc[mt][nt][2] + b1v;
            float v3 = acc[mt][nt][3] + b1v;
            *(float2*)(p0 + nt * 8) = make_float2(v0, v1);
            *(float2*)(p1 + nt * 8) = make_float2(v2, v3);
            s4[mt * 2 + 0] += v0 + v1;  q4[mt * 2 + 0] += v0 * v0 + v1 * v1;
            s4[mt * 2 + 1] += v2 + v3;  q4[mt * 2 + 1] += v2 * v2 + v3 * v3;
        }
    }
#pragma unroll
    for (int r = 0; r < 4; r++) {
        float s = s4[r], q = q4[r];
        s += __shfl_xor_sync(0xffffffffu, s, 1);
        s += __shfl_xor_sync(0xffffffffu, s, 2);
        q += __shfl_xor_sync(0xffffffffu, q, 1);
        q += __shfl_xor_sync(0xffffffffu, q, 2);
        if (tg == 0) {
            int lr = wm * 32 + (r >> 1) * 16 + (r & 1) * 8 + g;
            atomicAdd(&bst[lr], s);
            atomicAdd(&bst[128 + lr], q);
        }
    }
    __syncthreads();
    if (tid < 128) {
        atomicAdd(&g_sum[o_base + tid],   bst[tid]);
        atomicAdd(&g_sumsq[o_base + tid], bst[128 + tid]);
    }
}

// ---------------- kernel 4: finalize BN stats ----------------
__global__ void stats_kernel(const float* __restrict__ gamma,
                             const float* __restrict__ beta) {
    int c = threadIdx.x;
    const float inv_n = 1.0f / (float)(BB * NP);
    float mean = g_sum[c] * inv_n;
    float var  = g_sumsq[c] * inv_n - mean * mean;
    float inv  = 1.0f / sqrtf(var + 1e-5f);
    float sc   = gamma[c] * inv;
    g_scale[c] = sc;
    g_shift[c] = beta[c] - mean * sc;
}

// ---------------- kernel 5: apply BN + ReLU ----------------
__global__ void apply_kernel(float* __restrict__ out) {
    size_t i4 = (size_t)blockIdx.x * blockDim.x + threadIdx.x;
    float4 v = ((float4*)out)[i4];
    int o = (int)((i4 * 4) >> 13) & (COUT - 1);
    float s = g_scale[o], t = g_shift[o];
    v.x = fmaxf(v.x * s + t, 0.f);
    v.y = fmaxf(v.y * s + t, 0.f);
    v.z = fmaxf(v.z * s + t, 0.f);
    v.w = fmaxf(v.w * s + t, 0.f);
    ((float4*)out)[i4] = v;
}

// ---------------- launch ----------------
extern "C" void kernel_launch(void* const* d_in, const int* in_sizes, int n_in,
                              void* d_out, int out_size) {
    const float* x      = (const float*)d_in[0];
    const float* coords = (const float*)d_in[1];
    const float* rot    = (const float*)d_in[2];
    const float* dist   = (const float*)d_in[3];
    const float* W      = (const float*)d_in[4];
    const float* bias   = (const float*)d_in[5];
    const float* gamma  = (const float*)d_in[6];
    const float* beta   = (const float*)d_in[7];
    float* out = (float*)d_out;

    cudaFuncSetAttribute(conv12_kernel, cudaFuncAttributeMaxDynamicSharedMemorySize, SMEM_TOTAL);

    zero_sums_kernel<<<1, 256>>>();
    gweight_kernel<<<dim3(NP / 256, BB), 256>>>(coords, rot, dist);
    wfrag_kernel<<<(2 * NCHUNK * 4 * 8 * 32 + 255) / 256, 256>>>(W);
    conv12_kernel<<<dim3(NP / 128, COUT / 128, BB), 256, SMEM_TOTAL>>>(x, bias, out);
    stats_kernel<<<1, 256>>>(gamma, beta);
    apply_kernel<<<(BB * COUT * NP / 4) / 256, 256>>>(out);
}

// round 15
// speedup vs baseline: 1.5882x; 1.5882x over previous
#include <cuda_runtime.h>
#include <cuda_fp16.h>
#include <cstdint>
#include <math.h>

#define BB    8
#define CIN   256
#define COUT  256
#define NP    8192
#define KT    9
#define DILT  6
#define PADT  24
#define NCHUNK 36          // (KT * CIN) / 64

// ---------------- device scratch ----------------
__device__ float   g_gw[BB * KT * NP];              // gate weights [b][k][n]
__device__ uint8_t g_A8[2 * NCHUNK * 16384];        // pre-swizzled fp16 W tiles
__device__ float   g_sum[COUT];
__device__ float   g_sumsq[COUT];
__device__ float   g_scale[COUT];
__device__ float   g_shift[COUT];

// ---------------- helpers ----------------
__device__ __forceinline__ uint32_t smem_u32(const void* p) {
    uint32_t a;
    asm("{ .reg .u64 t; cvta.to.shared.u64 t, %1; cvt.u32.u64 %0, t; }" : "=r"(a) : "l"(p));
    return a;
}
#define SW128(off) ((off) ^ (((off) >> 3) & 0x70))

__device__ __forceinline__ void cp16(uint32_t dst, const void* src) {
    asm volatile("cp.async.cg.shared.global [%0], [%1], 16;" :: "r"(dst), "l"(src));
}
__device__ __forceinline__ void ldsm_x4(uint32_t* r, uint32_t addr) {
    asm volatile("ldmatrix.sync.aligned.m8n8.x4.shared.b16 {%0,%1,%2,%3}, [%4];"
        : "=r"(r[0]), "=r"(r[1]), "=r"(r[2]), "=r"(r[3]) : "r"(addr));
}
__device__ __forceinline__ void ldsm_x4t(uint32_t* r, uint32_t addr) {
    asm volatile("ldmatrix.sync.aligned.m8n8.x4.trans.shared.b16 {%0,%1,%2,%3}, [%4];"
        : "=r"(r[0]), "=r"(r[1]), "=r"(r[2]), "=r"(r[3]) : "r"(addr));
}
__device__ __forceinline__ void mma16816(float* c, const uint32_t* a, uint32_t b0, uint32_t b1) {
    asm volatile(
        "mma.sync.aligned.m16n8k16.row.col.f32.f16.f16.f32 "
        "{%0,%1,%2,%3}, {%4,%5,%6,%7}, {%8,%9}, {%0,%1,%2,%3};"
        : "+f"(c[0]), "+f"(c[1]), "+f"(c[2]), "+f"(c[3])
        : "r"(a[0]), "r"(a[1]), "r"(a[2]), "r"(a[3]), "r"(b0), "r"(b1));
}

// ---------------- kernel 0 ----------------
__global__ void zero_sums_kernel() {
    int t = threadIdx.x;
    g_sum[t] = 0.f;
    g_sumsq[t] = 0.f;
}

// ---------------- kernel 1: tap gate weights ----------------
__global__ void gweight_kernel(const float* __restrict__ coords,
                               const float* __restrict__ rot,
                               const float* __restrict__ dist) {
    int n = blockIdx.x * blockDim.x + threadIdx.x;
    int b = blockIdx.y;
    const float* cb = coords + (size_t)b * 3 * NP;
    const float* rb = rot    + (size_t)b * 3 * NP;

    float c0x = cb[n], c0y = cb[NP + n], c0z = cb[2 * NP + n];
    float r0x = rb[n], r0y = rb[NP + n], r0z = rb[2 * NP + n];
    float d0  = dist[(size_t)b * NP + n];
    float r0sq = r0x * r0x + r0y * r0y + r0z * r0z;

#pragma unroll
    for (int k = 0; k < KT; k++) {
        int j = n + k * DILT - PADT;
        float cjx = 0.f, cjy = 0.f, cjz = 0.f;
        float rjx = 0.f, rjy = 0.f, rjz = 0.f;
        float dj  = 0.f;
        if (j >= 0 && j < NP) {
            cjx = cb[j]; cjy = cb[NP + j]; cjz = cb[2 * NP + j];
            rjx = rb[j]; rjy = rb[NP + j]; rjz = rb[2 * NP + j];
            dj  = dist[(size_t)b * NP + j];
        }
        float dx = c0x - cjx, dy = c0y - cjy, dz = c0z - cjz;
        float dc = dx * dx + dy * dy + dz * dz;
        float dd = (d0 - dj) * (d0 - dj);
        float g  = expf(-0.5f * (dc + dd));
        float num  = r0x * rjx + r0y * rjy + r0z * rjz;
        float rjsq = rjx * rjx + rjy * rjy + rjz * rjz;
        float den  = sqrtf(r0sq * rjsq) + 1e-8f;
        g_gw[((size_t)b * KT + k) * NP + n] = g * fabsf(num / den);
    }
}

// ---------------- kernel 2: fp16 pre-swizzled W ----------------
__global__ void wsplit_kernel(const float* __restrict__ W) {
    int idx = blockIdx.x * 256 + threadIdx.x;
    if (idx >= 2 * NCHUNK * 128 * 64) return;
    int kc    = idx & 63;
    int t     = idx >> 6;
    int o_in  = t & 127;
    int t2    = t >> 7;
    int chunk = t2 % NCHUNK;
    int otile = t2 / NCHUNK;
    int k = chunk >> 2;
    int c = ((chunk & 3) << 6) + kc;
    int o = (otile << 7) + o_in;
    float val = W[((size_t)o * CIN + c) * KT + k];
    uint32_t sw = SW128((uint32_t)(o_in * 128 + kc * 2));
    size_t tb = (size_t)(otile * NCHUNK + chunk) * 16384;
    *(__half*)&g_A8[tb + sw] = __float2half(val);
}

// ---------------- SMEM layout ----------------
#define OFF_A   0          // 2 bufs x 16KB fp16 W          = 32768
#define OFF_B   32768      // 2 bufs x 16KB fp16 gated x    = 32768
#define OFF_ST  65536      // stats: 256 floats
#define SMEM_TOTAL 66560

// 2-column x ownership: thread owns cols [nn2, nn2+1], rows (tid>>6) + 4*(it + 8h).
// Warp loads 32 contiguous 8B segments -> fully coalesced for ALL taps (offsets
// are multiples of 6 floats = 24B = 8B-aligned; the old 4-col float2 path was
// 2x-uncoalesced on odd taps).

__device__ __forceinline__ void loadV2h(float2* vr,
                                        const float* __restrict__ xb,
                                        int n_base, int s, int tid, int h) {
    const int off   = (s >> 2) * DILT - PADT;
    const int c0    = (s & 3) << 6;
    const int nn2   = (tid & 63) << 1;           // float col (even)
    const int rbase = tid >> 6;                  // 0..3
    const int src   = n_base + off + nn2;
    const float* gs = xb + (size_t)(c0 + rbase) * NP + src;

    if (src >= 0 && src + 1 < NP) {              // interior (8B aligned always)
#pragma unroll
        for (int it = 0; it < 8; it++)
            vr[it] = *(const float2*)(gs + (size_t)(it + 8 * h) * 4 * NP);
    } else if (src + 1 < 0 || src >= NP) {       // fully OOB
#pragma unroll
        for (int it = 0; it < 8; it++)
            vr[it] = make_float2(0.f, 0.f);
    } else {                                     // straddle (1 element in)
#pragma unroll
        for (int it = 0; it < 8; it++) {
            const float* gp = gs + (size_t)(it + 8 * h) * 4 * NP;
            float e0 = (src >= 0 && src < NP)         ? gp[0] : 0.f;
            float e1 = (src + 1 >= 0 && src + 1 < NP) ? gp[1] : 0.f;
            vr[it] = make_float2(e0, e1);
        }
    }
}

// gate + fp16 + STS half into B tile ([kc 64][n 128], 256B swizzled rows).
// bofs is a BYTE OFFSET from smem base.
__device__ __forceinline__ void convertB2h(char* smem, uint32_t bofs, const float2* vr,
                                           int b, int n_base, int s, int tid, int h) {
    const int kk    = s >> 2;
    const int nn2   = (tid & 63) << 1;
    const int rbase = tid >> 6;
    const float2 g2 = *(const float2*)(g_gw + ((size_t)b * KT + kk) * NP + n_base + nn2);
#pragma unroll
    for (int it = 0; it < 8; it++) {
        int row = rbase + 4 * (it + 8 * h);
        float2 v = vr[it];
        __half2 hh = __floats2half2_rn(v.x * g2.x, v.y * g2.y);
        uint32_t ofs = (uint32_t)(row * 256) + (((uint32_t)(nn2 * 2)) ^ ((uint32_t)(row & 7) << 4));
        *(uint32_t*)(smem + bofs + ofs) = *(uint32_t*)&hh;
    }
}

// ---------------- kernel 3: HMMA fused gated dilated conv ----------------
__global__ void __launch_bounds__(256, 2) conv13_kernel(
    const float* __restrict__ x,
    const float* __restrict__ bias,
    float* __restrict__ out) {

    extern __shared__ __align__(16) char smem[];
    const uint32_t sbase = smem_u32(smem);

    const int tid  = threadIdx.x;
    const int lane = tid & 31;
    const int wid  = tid >> 5;
    const int wm = wid & 3;
    const int wn = wid >> 2;
    const int g  = lane >> 2;
    const int tg = lane & 3;

    const int b      = blockIdx.z;
    const int n_base = blockIdx.x * 128;
    const int otile  = blockIdx.y;
    const int o_base = otile * 128;

    const float*   xb   = x + (size_t)b * CIN * NP;
    const uint8_t* Asrc = g_A8 + (size_t)otile * NCHUNK * 16384;

    const int a_row   = wm * 32 + ((lane >> 3) & 1) * 8 + (lane & 7);
    const int a_kb    = ((lane >> 4) & 1) * 16;
    const int b_nbyte = wn * 128 + ((lane >> 4) << 4);
    const int b_kcl   = lane & 15;

    float acc[2][8][4];
#pragma unroll
    for (int mt = 0; mt < 2; mt++)
#pragma unroll
        for (int nt = 0; nt < 8; nt++)
#pragma unroll
            for (int r = 0; r < 4; r++) acc[mt][nt][r] = 0.f;

    float2 vr[8];

    // ---- prologue ----
    {
        const uint8_t* as = Asrc + tid * 16;
#pragma unroll
        for (int q = 0; q < 4; q++) cp16(sbase + OFF_A + tid * 16 + q * 4096, as + q * 4096);
        asm volatile("cp.async.commit_group;");
        loadV2h(vr, xb, n_base, 0, tid, 0);
        convertB2h(smem, OFF_B, vr, b, n_base, 0, tid, 0);
        loadV2h(vr, xb, n_base, 0, tid, 1);
        convertB2h(smem, OFF_B, vr, b, n_base, 0, tid, 1);
        asm volatile("cp.async.wait_group 0;" ::: "memory");   // A[0] landed
        __syncthreads();                                       // A[0], B[0] visible
        const uint8_t* as1 = Asrc + 16384 + tid * 16;
#pragma unroll
        for (int q = 0; q < 4; q++) cp16(sbase + OFF_A + 16384 + tid * 16 + q * 4096, as1 + q * 4096);
        asm volatile("cp.async.commit_group;");
    }

    // ---- mainloop: one sync per chunk, LDG prefetch interleaved with MMA halves ----
    for (int i = 0; i < NCHUNK; i++) {
        const int  cur = i & 1;
        const bool hn  = (i + 1 < NCHUNK);
        const uint32_t Ab    = sbase + OFF_A + cur * 16384;
        const uint32_t Bb    = sbase + OFF_B + cur * 16384;
        const uint32_t BnOfs = OFF_B + (cur ^ 1) * 16384;      // OFFSET into smem

        if (hn) loadV2h(vr, xb, n_base, i + 1, tid, 0);

        // compute ks = 0, 1
#pragma unroll
        for (int ks = 0; ks < 2; ks++) {
            uint32_t ah[2][4];
#pragma unroll
            for (int mt = 0; mt < 2; mt++) {
                uint32_t byte = (uint32_t)((a_row + mt * 16) * 128 + ks * 32 + a_kb);
                ldsm_x4(ah[mt], Ab + SW128(byte));
            }
            const int kc = ks * 16 + b_kcl;
            const uint32_t kb = (uint32_t)kc * 256;
            const uint32_t xm = ((uint32_t)kc & 7) << 4;
#pragma unroll
            for (int nt2 = 0; nt2 < 4; nt2++) {
                uint32_t br[4];
                const uint32_t nb = (uint32_t)(b_nbyte + nt2 * 32);
                ldsm_x4t(br, Bb + kb + (nb ^ xm));
#pragma unroll
                for (int mt = 0; mt < 2; mt++) {
                    mma16816(acc[mt][nt2 * 2 + 0], ah[mt], br[0], br[1]);
                    mma16816(acc[mt][nt2 * 2 + 1], ah[mt], br[2], br[3]);
                }
            }
        }

        if (hn) {
            convertB2h(smem, BnOfs, vr, b, n_base, i + 1, tid, 0);   // B[nxt] half0
            loadV2h(vr, xb, n_base, i + 1, tid, 1);
        }

        // compute ks = 2, 3
#pragma unroll
        for (int ks = 2; ks < 4; ks++) {
            uint32_t ah[2][4];
#pragma unroll
            for (int mt = 0; mt < 2; mt++) {
                uint32_t byte = (uint32_t)((a_row + mt * 16) * 128 + ks * 32 + a_kb);
                ldsm_x4(ah[mt], Ab + SW128(byte));
            }
            const int kc = ks * 16 + b_kcl;
            const uint32_t kb = (uint32_t)kc * 256;
            const uint32_t xm = ((uint32_t)kc & 7) << 4;
#pragma unroll
            for (int nt2 = 0; nt2 < 4; nt2++) {
                uint32_t br[4];
                const uint32_t nb = (uint32_t)(b_nbyte + nt2 * 32);
                ldsm_x4t(br, Bb + kb + (nb ^ xm));
#pragma unroll
                for (int mt = 0; mt < 2; mt++) {
                    mma16816(acc[mt][nt2 * 2 + 0], ah[mt], br[0], br[1]);
                    mma16816(acc[mt][nt2 * 2 + 1], ah[mt], br[2], br[3]);
                }
            }
        }

        if (hn) convertB2h(smem, BnOfs, vr, b, n_base, i + 1, tid, 1);  // B[nxt] half1

        asm volatile("cp.async.wait_group 0;" ::: "memory");   // A[i+1] landed
        __syncthreads();    // B[nxt]+A[i+1] visible; A[cur]/B[cur] free
        if (i + 2 < NCHUNK) {
            const uint8_t* as = Asrc + (size_t)(i + 2) * 16384 + tid * 16;
            const uint32_t ad = sbase + OFF_A + cur * 16384 + tid * 16;
#pragma unroll
            for (int q = 0; q < 4; q++) cp16(ad + q * 4096, as + q * 4096);
            asm volatile("cp.async.commit_group;");
        }
    }

    // ---- epilogue ----
    float* bst = (float*)(smem + OFF_ST);
    bst[tid] = 0.f;
    __syncthreads();

    float s4[4] = {0.f, 0.f, 0.f, 0.f}, q4[4] = {0.f, 0.f, 0.f, 0.f};
#pragma unroll
    for (int mt = 0; mt < 2; mt++) {
        const int r0v = wm * 32 + mt * 16 + g;
        const int r1v = r0v + 8;
        const float b0v = bias[o_base + r0v];
        const float b1v = bias[o_base + r1v];
        float* p0 = out + ((size_t)b * COUT + o_base + r0v) * NP + n_base + wn * 64 + 2 * tg;
        float* p1 = out + ((size_t)b * COUT + o_base + r1v) * NP + n_base + wn * 64 + 2 * tg;
#pragma unroll
        for (int nt = 0; nt < 8; nt++) {
            float v0 = acc[mt][nt][0] + b0v;
            float v1 = acc[mt][nt][1] + b0v;
            float v2 = acc[mt][nt][2] + b1v;
            float v3 = acc[mt][nt][3] + b1v;
            *(float2*)(p0 + nt * 8) = make_float2(v0, v1);
            *(float2*)(p1 + nt * 8) = make_float2(v2, v3);
            s4[mt * 2 + 0] += v0 + v1;  q4[mt * 2 + 0] += v0 * v0 + v1 * v1;
            s4[mt * 2 + 1] += v2 + v3;  q4[mt * 2 + 1] += v2 * v2 + v3 * v3;
        }
    }
#pragma unroll
    for (int r = 0; r < 4; r++) {
        float s = s4[r], q = q4[r];
        s += __shfl_xor_sync(0xffffffffu, s, 1);
        s += __shfl_xor_sync(0xffffffffu, s, 2);
        q += __shfl_xor_sync(0xffffffffu, q, 1);
        q += __shfl_xor_sync(0xffffffffu, q, 2);
        if (tg == 0) {
            int lr = wm * 32 + (r >> 1) * 16 + (r & 1) * 8 + g;
            atomicAdd(&bst[lr], s);
            atomicAdd(&bst[128 + lr], q);
        }
    }
    __syncthreads();
    if (tid < 128) {
        atomicAdd(&g_sum[o_base + tid],   bst[tid]);
        atomicAdd(&g_sumsq[o_base + tid], bst[128 + tid]);
    }
}

// ---------------- kernel 4: finalize BN stats ----------------
__global__ void stats_kernel(const float* __restrict__ gamma,
                             const float* __restrict__ beta) {
    int c = threadIdx.x;
    const float inv_n = 1.0f / (float)(BB * NP);
    float mean = g_sum[c] * inv_n;
    float var  = g_sumsq[c] * inv_n - mean * mean;
    float inv  = 1.0f / sqrtf(var + 1e-5f);
    float sc   = gamma[c] * inv;
    g_scale[c] = sc;
    g_shift[c] = beta[c] - mean * sc;
}

// ---------------- kernel 5: apply BN + ReLU ----------------
__global__ void apply_kernel(float* __restrict__ out) {
    size_t i4 = (size_t)blockIdx.x * blockDim.x + threadIdx.x;
    float4 v = ((float4*)out)[i4];
    int o = (int)((i4 * 4) >> 13) & (COUT - 1);
    float s = g_scale[o], t = g_shift[o];
    v.x = fmaxf(v.x * s + t, 0.f);
    v.y = fmaxf(v.y * s + t, 0.f);
    v.z = fmaxf(v.z * s + t, 0.f);
    v.w = fmaxf(v.w * s + t, 0.f);
    ((float4*)out)[i4] = v;
}

// ---------------- launch ----------------
extern "C" void kernel_launch(void* const* d_in, const int* in_sizes, int n_in,
                              void* d_out, int out_size) {
    const float* x      = (const float*)d_in[0];
    const float* coords = (const float*)d_in[1];
    const float* rot    = (const float*)d_in[2];
    const float* dist   = (const float*)d_in[3];
    const float* W      = (const float*)d_in[4];
    const float* bias   = (const float*)d_in[5];
    const float* gamma  = (const float*)d_in[6];
    const float* beta   = (const float*)d_in[7];
    float* out = (float*)d_out;

    cudaFuncSetAttribute(conv13_kernel, cudaFuncAttributeMaxDynamicSharedMemorySize, SMEM_TOTAL);

    zero_sums_kernel<<<1, 256>>>();
    gweight_kernel<<<dim3(NP / 256, BB), 256>>>(coords, rot, dist);
    wsplit_kernel<<<(2 * NCHUNK * 128 * 64 + 255) / 256, 256>>>(W);
    conv13_kernel<<<dim3(NP / 128, COUT / 128, BB), 256, SMEM_TOTAL>>>(x, bias, out);
    stats_kernel<<<1, 256>>>(gamma, beta);
    apply_kernel<<<(BB * COUT * NP / 4) / 256, 256>>>(out);
}

// round 16
// speedup vs baseline: 1.7384x; 1.0946x over previous
#include <cuda_runtime.h>
#include <cuda_fp16.h>
#include <cstdint>
#include <math.h>

#define BB    8
#define CIN   256
#define COUT  256
#define NP    8192
#define KT    9
#define DILT  6
#define PADT  24
#define NCHUNK 36          // (KT * CIN) / 64
#define BPITCH 272         // B row pitch (bytes): 256 data + 16 pad -> conflict-free, no XOR

// ---------------- device scratch ----------------
__device__ float   g_gw[BB * KT * NP];              // gate weights [b][k][n]
__device__ uint8_t g_A8[2 * NCHUNK * 16384];        // pre-swizzled fp16 W tiles
__device__ float   g_sum[COUT];
__device__ float   g_sumsq[COUT];
__device__ float   g_scale[COUT];
__device__ float   g_shift[COUT];

// ---------------- helpers ----------------
__device__ __forceinline__ uint32_t smem_u32(const void* p) {
    uint32_t a;
    asm("{ .reg .u64 t; cvta.to.shared.u64 t, %1; cvt.u32.u64 %0, t; }" : "=r"(a) : "l"(p));
    return a;
}
#define SW128(off) ((off) ^ (((off) >> 3) & 0x70))

__device__ __forceinline__ void cp16(uint32_t dst, const void* src) {
    asm volatile("cp.async.cg.shared.global [%0], [%1], 16;" :: "r"(dst), "l"(src));
}
__device__ __forceinline__ void ldsm_x4(uint32_t* r, uint32_t addr) {
    asm volatile("ldmatrix.sync.aligned.m8n8.x4.shared.b16 {%0,%1,%2,%3}, [%4];"
        : "=r"(r[0]), "=r"(r[1]), "=r"(r[2]), "=r"(r[3]) : "r"(addr));
}
__device__ __forceinline__ void ldsm_x4t(uint32_t* r, uint32_t addr) {
    asm volatile("ldmatrix.sync.aligned.m8n8.x4.trans.shared.b16 {%0,%1,%2,%3}, [%4];"
        : "=r"(r[0]), "=r"(r[1]), "=r"(r[2]), "=r"(r[3]) : "r"(addr));
}
__device__ __forceinline__ void mma16816(float* c, const uint32_t* a, uint32_t b0, uint32_t b1) {
    asm volatile(
        "mma.sync.aligned.m16n8k16.row.col.f32.f16.f16.f32 "
        "{%0,%1,%2,%3}, {%4,%5,%6,%7}, {%8,%9}, {%0,%1,%2,%3};"
        : "+f"(c[0]), "+f"(c[1]), "+f"(c[2]), "+f"(c[3])
        : "r"(a[0]), "r"(a[1]), "r"(a[2]), "r"(a[3]), "r"(b0), "r"(b1));
}

// ---------------- kernel 0 ----------------
__global__ void zero_sums_kernel() {
    int t = threadIdx.x;
    g_sum[t] = 0.f;
    g_sumsq[t] = 0.f;
}

// ---------------- kernel 1: tap gate weights ----------------
__global__ void gweight_kernel(const float* __restrict__ coords,
                               const float* __restrict__ rot,
                               const float* __restrict__ dist) {
    int n = blockIdx.x * blockDim.x + threadIdx.x;
    int b = blockIdx.y;
    const float* cb = coords + (size_t)b * 3 * NP;
    const float* rb = rot    + (size_t)b * 3 * NP;

    float c0x = cb[n], c0y = cb[NP + n], c0z = cb[2 * NP + n];
    float r0x = rb[n], r0y = rb[NP + n], r0z = rb[2 * NP + n];
    float d0  = dist[(size_t)b * NP + n];
    float r0sq = r0x * r0x + r0y * r0y + r0z * r0z;

#pragma unroll
    for (int k = 0; k < KT; k++) {
        int j = n + k * DILT - PADT;
        float cjx = 0.f, cjy = 0.f, cjz = 0.f;
        float rjx = 0.f, rjy = 0.f, rjz = 0.f;
        float dj  = 0.f;
        if (j >= 0 && j < NP) {
            cjx = cb[j]; cjy = cb[NP + j]; cjz = cb[2 * NP + j];
            rjx = rb[j]; rjy = rb[NP + j]; rjz = rb[2 * NP + j];
            dj  = dist[(size_t)b * NP + j];
        }
        float dx = c0x - cjx, dy = c0y - cjy, dz = c0z - cjz;
        float dc = dx * dx + dy * dy + dz * dz;
        float dd = (d0 - dj) * (d0 - dj);
        float g  = expf(-0.5f * (dc + dd));
        float num  = r0x * rjx + r0y * rjy + r0z * rjz;
        float rjsq = rjx * rjx + rjy * rjy + rjz * rjz;
        float den  = sqrtf(r0sq * rjsq) + 1e-8f;
        g_gw[((size_t)b * KT + k) * NP + n] = g * fabsf(num / den);
    }
}

// ---------------- kernel 2: fp16 pre-swizzled W ----------------
__global__ void wsplit_kernel(const float* __restrict__ W) {
    int idx = blockIdx.x * 256 + threadIdx.x;
    if (idx >= 2 * NCHUNK * 128 * 64) return;
    int kc    = idx & 63;
    int t     = idx >> 6;
    int o_in  = t & 127;
    int t2    = t >> 7;
    int chunk = t2 % NCHUNK;
    int otile = t2 / NCHUNK;
    int k = chunk >> 2;
    int c = ((chunk & 3) << 6) + kc;
    int o = (otile << 7) + o_in;
    float val = W[((size_t)o * CIN + c) * KT + k];
    uint32_t sw = SW128((uint32_t)(o_in * 128 + kc * 2));
    size_t tb = (size_t)(otile * NCHUNK + chunk) * 16384;
    *(__half*)&g_A8[tb + sw] = __float2half(val);
}

// ---------------- SMEM layout ----------------
#define OFF_A    0                       // 2 bufs x 16KB fp16 W = 32768
#define BBUF     (64 * BPITCH)           // 17408
#define OFF_B    32768                   // 2 bufs x 17408 = 34816
#define OFF_ST   (OFF_B + 2 * BBUF)      // 67584: stats 256 floats
#define SMEM_TOTAL (OFF_ST + 1024)       // 68608

// ---- load quarter q of raw x for chunk s into 4 float2 regs ----
// thread owns cols [nn2, nn2+1], kc rows rbase + 16q + 4*it (it<4).
__device__ __forceinline__ void loadV2q(float2* vr,
                                        const float* __restrict__ xb,
                                        int n_base, int s, int tid, int q) {
    const int off   = (s >> 2) * DILT - PADT;
    const int c0    = (s & 3) << 6;
    const int nn2   = (tid & 63) << 1;
    const int rbase = tid >> 6;                  // 0..3
    const int src   = n_base + off + nn2;
    const float* gs = xb + (size_t)(c0 + rbase + 16 * q) * NP + src;

    if (src >= 0 && src + 1 < NP) {              // interior (8B aligned always)
#pragma unroll
        for (int it = 0; it < 4; it++)
            vr[it] = *(const float2*)(gs + (size_t)it * 4 * NP);
    } else if (src + 1 < 0 || src >= NP) {       // fully OOB
#pragma unroll
        for (int it = 0; it < 4; it++)
            vr[it] = make_float2(0.f, 0.f);
    } else {                                     // straddle (rare edge)
#pragma unroll
        for (int it = 0; it < 4; it++) {
            const float* gp = gs + (size_t)it * 4 * NP;
            float e0 = (src >= 0 && src < NP)         ? gp[0] : 0.f;
            float e1 = (src + 1 >= 0 && src + 1 < NP) ? gp[1] : 0.f;
            vr[it] = make_float2(e0, e1);
        }
    }
}

// ---- gate + fp16 + STS quarter into B tile ([kc 64][n 128], pitch-272 rows) ----
__device__ __forceinline__ void convertB2q(char* smem, uint32_t bofs, const float2* vr,
                                           float2 g2, int tid, int q) {
    const int nn2   = (tid & 63) << 1;
    const int rbase = tid >> 6;
    char* bp = smem + bofs + (size_t)(rbase + 16 * q) * BPITCH + nn2 * 2;
#pragma unroll
    for (int it = 0; it < 4; it++) {
        float2 v = vr[it];
        __half2 hh = __floats2half2_rn(v.x * g2.x, v.y * g2.y);
        *(uint32_t*)(bp + (size_t)it * 4 * BPITCH) = *(uint32_t*)&hh;
    }
}

// ---------------- kernel 3: HMMA fused gated dilated conv ----------------
__global__ void __launch_bounds__(256, 2) conv14_kernel(
    const float* __restrict__ x,
    const float* __restrict__ bias,
    float* __restrict__ out) {

    extern __shared__ __align__(16) char smem[];
    const uint32_t sbase = smem_u32(smem);

    const int tid  = threadIdx.x;
    const int lane = tid & 31;
    const int wid  = tid >> 5;
    const int wm = wid & 3;
    const int wn = wid >> 2;
    const int g  = lane >> 2;
    const int tg = lane & 3;

    const int b      = blockIdx.z;
    const int n_base = blockIdx.x * 128;
    const int otile  = blockIdx.y;
    const int o_base = otile * 128;

    const float*   xb   = x + (size_t)b * CIN * NP;
    const uint8_t* Asrc = g_A8 + (size_t)otile * NCHUNK * 16384;

    const int a_row = wm * 32 + ((lane >> 3) & 1) * 8 + (lane & 7);
    const int a_kb  = ((lane >> 4) & 1) * 16;
    // per-lane B base offset: row (lane&15) * pitch + n-col bytes
    const uint32_t b_lane = (uint32_t)((lane & 15) * BPITCH + wn * 128 + ((lane >> 4) << 4));
    const int nn2 = (tid & 63) << 1;     // for gate load

    float acc[2][8][4];
#pragma unroll
    for (int mt = 0; mt < 2; mt++)
#pragma unroll
        for (int nt = 0; nt < 8; nt++)
#pragma unroll
            for (int r = 0; r < 4; r++) acc[mt][nt][r] = 0.f;

    float2 vq[4];

    // ---- prologue: A[0],A[1] cp.async; B[0] staged in quarters ----
    {
        const uint8_t* as = Asrc + tid * 16;
#pragma unroll
        for (int q = 0; q < 4; q++) cp16(sbase + OFF_A + tid * 16 + q * 4096, as + q * 4096);
        asm volatile("cp.async.commit_group;");
        float2 g2 = *(const float2*)(g_gw + (size_t)b * KT * NP + n_base + nn2);  // tap 0
#pragma unroll
        for (int q = 0; q < 4; q++) {
            loadV2q(vq, xb, n_base, 0, tid, q);
            convertB2q(smem, OFF_B, vq, g2, tid, q);
        }
        asm volatile("cp.async.wait_group 0;" ::: "memory");   // A[0] landed
        __syncthreads();                                       // A[0], B[0] visible
        const uint8_t* as1 = Asrc + 16384 + tid * 16;
#pragma unroll
        for (int q = 0; q < 4; q++) cp16(sbase + OFF_A + 16384 + tid * 16 + q * 4096, as1 + q * 4096);
        asm volatile("cp.async.commit_group;");
    }

    // ---- mainloop: one sync per chunk, quarter-granular staging between ks blocks ----
    for (int i = 0; i < NCHUNK; i++) {
        const int  cur = i & 1;
        const bool hn  = (i + 1 < NCHUNK);
        const uint32_t Ab    = sbase + OFF_A + cur * 16384;
        const uint32_t Bb    = sbase + OFF_B + cur * BBUF + b_lane;
        const uint32_t BnOfs = OFF_B + (cur ^ 1) * BBUF;

        float2 g2;
        if (hn) {
            g2 = *(const float2*)(g_gw + ((size_t)b * KT + ((i + 1) >> 2)) * NP + n_base + nn2);
            loadV2q(vq, xb, n_base, i + 1, tid, 0);
        }

#pragma unroll
        for (int ks = 0; ks < 4; ks++) {
            uint32_t ah[2][4];
#pragma unroll
            for (int mt = 0; mt < 2; mt++) {
                uint32_t byte = (uint32_t)((a_row + mt * 16) * 128 + ks * 32 + a_kb);
                ldsm_x4(ah[mt], Ab + SW128(byte));
            }
            const uint32_t Bks = Bb + (uint32_t)(ks * 16 * BPITCH);
#pragma unroll
            for (int nt2 = 0; nt2 < 4; nt2++) {
                uint32_t br[4];
                ldsm_x4t(br, Bks + nt2 * 32);
#pragma unroll
                for (int mt = 0; mt < 2; mt++) {
                    mma16816(acc[mt][nt2 * 2 + 0], ah[mt], br[0], br[1]);
                    mma16816(acc[mt][nt2 * 2 + 1], ah[mt], br[2], br[3]);
                }
            }
            if (hn) {
                convertB2q(smem, BnOfs, vq, g2, tid, ks);
                if (ks < 3) loadV2q(vq, xb, n_base, i + 1, tid, ks + 1);
            }
        }

        asm volatile("cp.async.wait_group 0;" ::: "memory");   // A[i+1] landed
        __syncthreads();    // B[nxt]+A[i+1] visible; A[cur]/B[cur] free
        if (i + 2 < NCHUNK) {
            const uint8_t* as = Asrc + (size_t)(i + 2) * 16384 + tid * 16;
            const uint32_t ad = sbase + OFF_A + cur * 16384 + tid * 16;
#pragma unroll
            for (int q = 0; q < 4; q++) cp16(ad + q * 4096, as + q * 4096);
            asm volatile("cp.async.commit_group;");
        }
    }

    // ---- epilogue ----
    float* bst = (float*)(smem + OFF_ST);
    bst[tid] = 0.f;
    __syncthreads();

    float s4[4] = {0.f, 0.f, 0.f, 0.f}, q4[4] = {0.f, 0.f, 0.f, 0.f};
#pragma unroll
    for (int mt = 0; mt < 2; mt++) {
        const int r0v = wm * 32 + mt * 16 + g;
        const int r1v = r0v + 8;
        const float b0v = bias[o_base + r0v];
        const float b1v = bias[o_base + r1v];
        float* p0 = out + ((size_t)b * COUT + o_base + r0v) * NP + n_base + wn * 64 + 2 * tg;
        float* p1 = out + ((size_t)b * COUT + o_base + r1v) * NP + n_base + wn * 64 + 2 * tg;
#pragma unroll
        for (int nt = 0; nt < 8; nt++) {
            float v0 = acc[mt][nt][0] + b0v;
            float v1 = acc[mt][nt][1] + b0v;
            float v2 = acc[mt][nt][2] + b1v;
            float v3 = acc[mt][nt][3] + b1v;
            *(float2*)(p0 + nt * 8) = make_float2(v0, v1);
            *(float2*)(p1 + nt * 8) = make_float2(v2, v3);
            s4[mt * 2 + 0] += v0 + v1;  q4[mt * 2 + 0] += v0 * v0 + v1 * v1;
            s4[mt * 2 + 1] += v2 + v3;  q4[mt * 2 + 1] += v2 * v2 + v3 * v3;
        }
    }
#pragma unroll
    for (int r = 0; r < 4; r++) {
        float s = s4[r], q = q4[r];
        s += __shfl_xor_sync(0xffffffffu, s, 1);
        s += __shfl_xor_sync(0xffffffffu, s, 2);
        q += __shfl_xor_sync(0xffffffffu, q, 1);
        q += __shfl_xor_sync(0xffffffffu, q, 2);
        if (tg == 0) {
            int lr = wm * 32 + (r >> 1) * 16 + (r & 1) * 8 + g;
            atomicAdd(&bst[lr], s);
            atomicAdd(&bst[128 + lr], q);
        }
    }
    __syncthreads();
    if (tid < 128) {
        atomicAdd(&g_sum[o_base + tid],   bst[tid]);
        atomicAdd(&g_sumsq[o_base + tid], bst[128 + tid]);
    }
}

// ---------------- kernel 4: finalize BN stats ----------------
__global__ void stats_kernel(const float* __restrict__ gamma,
                             const float* __restrict__ beta) {
    int c = threadIdx.x;
    const float inv_n = 1.0f / (float)(BB * NP);
    float mean = g_sum[c] * inv_n;
    float var  = g_sumsq[c] * inv_n - mean * mean;
    float inv  = 1.0f / sqrtf(var + 1e-5f);
    float sc   = gamma[c] * inv;
    g_scale[c] = sc;
    g_shift[c] = beta[c] - mean * sc;
}

// ---------------- kernel 5: apply BN + ReLU ----------------
__global__ void apply_kernel(float* __restrict__ out) {
    size_t i4 = (size_t)blockIdx.x * blockDim.x + threadIdx.x;
    float4 v = ((float4*)out)[i4];
    int o = (int)((i4 * 4) >> 13) & (COUT - 1);
    float s = g_scale[o], t = g_shift[o];
    v.x = fmaxf(v.x * s + t, 0.f);
    v.y = fmaxf(v.y * s + t, 0.f);
    v.z = fmaxf(v.z * s + t, 0.f);
    v.w = fmaxf(v.w * s + t, 0.f);
    ((float4*)out)[i4] = v;
}

// ---------------- launch ----------------
extern "C" void kernel_launch(void* const* d_in, const int* in_sizes, int n_in,
                              void* d_out, int out_size) {
    const float* x      = (const float*)d_in[0];
    const float* coords = (const float*)d_in[1];
    const float* rot    = (const float*)d_in[2];
    const float* dist   = (const float*)d_in[3];
    const float* W      = (const float*)d_in[4];
    const float* bias   = (const float*)d_in[5];
    const float* gamma  = (const float*)d_in[6];
    const float* beta   = (const float*)d_in[7];
    float* out = (float*)d_out;

    cudaFuncSetAttribute(conv14_kernel, cudaFuncAttributeMaxDynamicSharedMemorySize, SMEM_TOTAL);

    zero_sums_kernel<<<1, 256>>>();
    gweight_kernel<<<dim3(NP / 256, BB), 256>>>(coords, rot, dist);
    wsplit_kernel<<<(2 * NCHUNK * 128 * 64 + 255) / 256, 256>>>(W);
    conv14_kernel<<<dim3(NP / 128, COUT / 128, BB), 256, SMEM_TOTAL>>>(x, bias, out);
    stats_kernel<<<1, 256>>>(gamma, beta);
    apply_kernel<<<(BB * COUT * NP / 4) / 256, 256>>>(out);
}

// round 17
// speedup vs baseline: 1.7498x; 1.0065x over previous
#include <cuda_runtime.h>
#include <cuda_fp16.h>
#include <cstdint>
#include <math.h>

#define BB    8
#define CIN   256
#define COUT  256
#define NP    8192
#define KT    9
#define DILT  6
#define PADT  24
#define NCHUNK 36          // (KT * CIN) / 64
#define BPITCH 272         // B row pitch (bytes): 256 data + 16 pad -> conflict-free, no XOR

// ---------------- device scratch ----------------
__device__ float   g_gw[BB * KT * NP];              // gate weights [b][k][n]
__device__ uint8_t g_A8[2 * NCHUNK * 16384];        // pre-swizzled fp16 W tiles
__device__ float   g_sum[COUT];
__device__ float   g_sumsq[COUT];
__device__ float   g_scale[COUT];
__device__ float   g_shift[COUT];

// ---------------- helpers ----------------
__device__ __forceinline__ uint32_t smem_u32(const void* p) {
    uint32_t a;
    asm("{ .reg .u64 t; cvta.to.shared.u64 t, %1; cvt.u32.u64 %0, t; }" : "=r"(a) : "l"(p));
    return a;
}
#define SW128(off) ((off) ^ (((off) >> 3) & 0x70))

__device__ __forceinline__ void cp16(uint32_t dst, const void* src) {
    asm volatile("cp.async.cg.shared.global [%0], [%1], 16;" :: "r"(dst), "l"(src));
}
__device__ __forceinline__ void ldsm_x4(uint32_t* r, uint32_t addr) {
    asm volatile("ldmatrix.sync.aligned.m8n8.x4.shared.b16 {%0,%1,%2,%3}, [%4];"
        : "=r"(r[0]), "=r"(r[1]), "=r"(r[2]), "=r"(r[3]) : "r"(addr));
}
__device__ __forceinline__ void ldsm_x4t(uint32_t* r, uint32_t addr) {
    asm volatile("ldmatrix.sync.aligned.m8n8.x4.trans.shared.b16 {%0,%1,%2,%3}, [%4];"
        : "=r"(r[0]), "=r"(r[1]), "=r"(r[2]), "=r"(r[3]) : "r"(addr));
}
__device__ __forceinline__ void mma16816(float* c, const uint32_t* a, uint32_t b0, uint32_t b1) {
    asm volatile(
        "mma.sync.aligned.m16n8k16.row.col.f32.f16.f16.f32 "
        "{%0,%1,%2,%3}, {%4,%5,%6,%7}, {%8,%9}, {%0,%1,%2,%3};"
        : "+f"(c[0]), "+f"(c[1]), "+f"(c[2]), "+f"(c[3])
        : "r"(a[0]), "r"(a[1]), "r"(a[2]), "r"(a[3]), "r"(b0), "r"(b1));
}

// ---------------- kernel 1: fused prep (zero stats + gate weights + W pack) ----------------
// block 0                : zero g_sum/g_sumsq
// blocks 1..256          : gweight (256 blocks: 32 n-blocks x 8 b)
// blocks 257..2560       : wsplit  (2304 blocks)
__global__ void prep_kernel(const float* __restrict__ coords,
                            const float* __restrict__ rot,
                            const float* __restrict__ dist,
                            const float* __restrict__ W) {
    const int bid = blockIdx.x;
    const int tid = threadIdx.x;

    if (bid == 0) {
        g_sum[tid] = 0.f;
        g_sumsq[tid] = 0.f;
        return;
    }
    if (bid <= 256) {
        int gwid = bid - 1;
        int n = (gwid & 31) * 256 + tid;
        int b = gwid >> 5;
        const float* cb = coords + (size_t)b * 3 * NP;
        const float* rb = rot    + (size_t)b * 3 * NP;

        float c0x = cb[n], c0y = cb[NP + n], c0z = cb[2 * NP + n];
        float r0x = rb[n], r0y = rb[NP + n], r0z = rb[2 * NP + n];
        float d0  = dist[(size_t)b * NP + n];
        float r0sq = r0x * r0x + r0y * r0y + r0z * r0z;

#pragma unroll
        for (int k = 0; k < KT; k++) {
            int j = n + k * DILT - PADT;
            float cjx = 0.f, cjy = 0.f, cjz = 0.f;
            float rjx = 0.f, rjy = 0.f, rjz = 0.f;
            float dj  = 0.f;
            if (j >= 0 && j < NP) {
                cjx = cb[j]; cjy = cb[NP + j]; cjz = cb[2 * NP + j];
                rjx = rb[j]; rjy = rb[NP + j]; rjz = rb[2 * NP + j];
                dj  = dist[(size_t)b * NP + j];
            }
            float dx = c0x - cjx, dy = c0y - cjy, dz = c0z - cjz;
            float dc = dx * dx + dy * dy + dz * dz;
            float dd = (d0 - dj) * (d0 - dj);
            float g  = expf(-0.5f * (dc + dd));
            float num  = r0x * rjx + r0y * rjy + r0z * rjz;
            float rjsq = rjx * rjx + rjy * rjy + rjz * rjz;
            float den  = sqrtf(r0sq * rjsq) + 1e-8f;
            g_gw[((size_t)b * KT + k) * NP + n] = g * fabsf(num / den);
        }
        return;
    }
    // wsplit
    {
        int idx = (bid - 257) * 256 + tid;
        if (idx >= 2 * NCHUNK * 128 * 64) return;
        int kc    = idx & 63;
        int t     = idx >> 6;
        int o_in  = t & 127;
        int t2    = t >> 7;
        int chunk = t2 % NCHUNK;
        int otile = t2 / NCHUNK;
        int k = chunk >> 2;
        int c = ((chunk & 3) << 6) + kc;
        int o = (otile << 7) + o_in;
        float val = W[((size_t)o * CIN + c) * KT + k];
        uint32_t sw = SW128((uint32_t)(o_in * 128 + kc * 2));
        size_t tb = (size_t)(otile * NCHUNK + chunk) * 16384;
        *(__half*)&g_A8[tb + sw] = __float2half(val);
    }
}

// ---------------- SMEM layout ----------------
#define OFF_A    0                       // 3 bufs x 16KB fp16 W = 49152
#define BBUF     (64 * BPITCH)           // 17408
#define OFF_B    49152                   // 2 bufs x 17408 = 34816
#define OFF_ST   (OFF_B + 2 * BBUF)      // 83968: stats 256 floats
#define SMEM_TOTAL (OFF_ST + 1024)       // 84992

// ---- load quarter q of raw x for chunk s into 4 float2 regs ----
__device__ __forceinline__ void loadV2q(float2* vr,
                                        const float* __restrict__ xb,
                                        int n_base, int s, int tid, int q) {
    const int off   = (s >> 2) * DILT - PADT;
    const int c0    = (s & 3) << 6;
    const int nn2   = (tid & 63) << 1;
    const int rbase = tid >> 6;                  // 0..3
    const int src   = n_base + off + nn2;
    const float* gs = xb + (size_t)(c0 + rbase + 16 * q) * NP + src;

    if (src >= 0 && src + 1 < NP) {              // interior (8B aligned always)
#pragma unroll
        for (int it = 0; it < 4; it++)
            vr[it] = *(const float2*)(gs + (size_t)it * 4 * NP);
    } else if (src + 1 < 0 || src >= NP) {       // fully OOB
#pragma unroll
        for (int it = 0; it < 4; it++)
            vr[it] = make_float2(0.f, 0.f);
    } else {                                     // straddle (rare edge)
#pragma unroll
        for (int it = 0; it < 4; it++) {
            const float* gp = gs + (size_t)it * 4 * NP;
            float e0 = (src >= 0 && src < NP)         ? gp[0] : 0.f;
            float e1 = (src + 1 >= 0 && src + 1 < NP) ? gp[1] : 0.f;
            vr[it] = make_float2(e0, e1);
        }
    }
}

// ---- gate + fp16 + STS quarter into B tile ([kc 64][n 128], pitch-272 rows) ----
__device__ __forceinline__ void convertB2q(char* smem, uint32_t bofs, const float2* vr,
                                           float2 g2, int tid, int q) {
    const int nn2   = (tid & 63) << 1;
    const int rbase = tid >> 6;
    char* bp = smem + bofs + (size_t)(rbase + 16 * q) * BPITCH + nn2 * 2;
#pragma unroll
    for (int it = 0; it < 4; it++) {
        float2 v = vr[it];
        __half2 hh = __floats2half2_rn(v.x * g2.x, v.y * g2.y);
        *(uint32_t*)(bp + (size_t)it * 4 * BPITCH) = *(uint32_t*)&hh;
    }
}

// ---------------- kernel 2: HMMA fused gated dilated conv ----------------
__global__ void __launch_bounds__(256, 2) conv15_kernel(
    const float* __restrict__ x,
    const float* __restrict__ bias,
    float* __restrict__ out) {

    extern __shared__ __align__(16) char smem[];
    const uint32_t sbase = smem_u32(smem);

    const int tid  = threadIdx.x;
    const int lane = tid & 31;
    const int wid  = tid >> 5;
    const int wm = wid & 3;
    const int wn = wid >> 2;
    const int g  = lane >> 2;
    const int tg = lane & 3;

    const int b      = blockIdx.z;
    const int n_base = blockIdx.x * 128;
    const int otile  = blockIdx.y;
    const int o_base = otile * 128;

    const float*   xb   = x + (size_t)b * CIN * NP;
    const uint8_t* Asrc = g_A8 + (size_t)otile * NCHUNK * 16384;

    const int a_row = wm * 32 + ((lane >> 3) & 1) * 8 + (lane & 7);
    const int a_kb  = ((lane >> 4) & 1) * 16;
    const uint32_t b_lane = (uint32_t)((lane & 15) * BPITCH + wn * 128 + ((lane >> 4) << 4));
    const int nn2 = (tid & 63) << 1;

    float acc[2][8][4];
#pragma unroll
    for (int mt = 0; mt < 2; mt++)
#pragma unroll
        for (int nt = 0; nt < 8; nt++)
#pragma unroll
            for (int r = 0; r < 4; r++) acc[mt][nt][r] = 0.f;

    float2 vq[4];

    // ---- prologue: A[0], A[1] cp.async (2 groups); B[0] staged in quarters ----
    {
        const uint8_t* as = Asrc + tid * 16;
#pragma unroll
        for (int q = 0; q < 4; q++) cp16(sbase + OFF_A + tid * 16 + q * 4096, as + q * 4096);
        asm volatile("cp.async.commit_group;");
        const uint8_t* as1 = Asrc + 16384 + tid * 16;
#pragma unroll
        for (int q = 0; q < 4; q++) cp16(sbase + OFF_A + 16384 + tid * 16 + q * 4096, as1 + q * 4096);
        asm volatile("cp.async.commit_group;");

        float2 g2 = *(const float2*)(g_gw + (size_t)b * KT * NP + n_base + nn2);  // tap 0
#pragma unroll
        for (int q = 0; q < 4; q++) {
            loadV2q(vq, xb, n_base, 0, tid, q);
            convertB2q(smem, OFF_B, vq, g2, tid, q);
        }
        asm volatile("cp.async.wait_group 1;" ::: "memory");   // A[0] landed (A[1] may pend)
        __syncthreads();                                       // A[0], B[0] visible
    }

    // A buffer rotation indices (i % 3), updated incrementally
    int ai = 0;    // buffer of chunk i
    int ap = 2;    // buffer of chunk i+2

    // ---- mainloop: one sync per chunk; A cp hoisted into ks0; wait_group 1 ----
    for (int i = 0; i < NCHUNK; i++) {
        const int  cur = i & 1;
        const bool hn  = (i + 1 < NCHUNK);
        const uint32_t Ab    = sbase + OFF_A + ai * 16384;
        const uint32_t Bb    = sbase + OFF_B + cur * BBUF + b_lane;
        const uint32_t BnOfs = OFF_B + (cur ^ 1) * BBUF;

        float2 g2;
        if (hn) {
            g2 = *(const float2*)(g_gw + ((size_t)b * KT + ((i + 1) >> 2)) * NP + n_base + nn2);
            loadV2q(vq, xb, n_base, i + 1, tid, 0);
        }

#pragma unroll
        for (int ks = 0; ks < 4; ks++) {
            uint32_t ah[2][4];
#pragma unroll
            for (int mt = 0; mt < 2; mt++) {
                uint32_t byte = (uint32_t)((a_row + mt * 16) * 128 + ks * 32 + a_kb);
                ldsm_x4(ah[mt], Ab + SW128(byte));
            }
            const uint32_t Bks = Bb + (uint32_t)(ks * 16 * BPITCH);
#pragma unroll
            for (int nt2 = 0; nt2 < 4; nt2++) {
                uint32_t br[4];
                ldsm_x4t(br, Bks + nt2 * 32);
#pragma unroll
                for (int mt = 0; mt < 2; mt++) {
                    mma16816(acc[mt][nt2 * 2 + 0], ah[mt], br[0], br[1]);
                    mma16816(acc[mt][nt2 * 2 + 1], ah[mt], br[2], br[3]);
                }
            }
            if (ks == 0 && i + 2 < NCHUNK) {
                // hoisted A prefetch for chunk i+2 into the third buffer
                const uint8_t* as = Asrc + (size_t)(i + 2) * 16384 + tid * 16;
                const uint32_t ad = sbase + OFF_A + ap * 16384 + tid * 16;
#pragma unroll
                for (int q = 0; q < 4; q++) cp16(ad + q * 4096, as + q * 4096);
                asm volatile("cp.async.commit_group;");
            }
            if (hn) {
                convertB2q(smem, BnOfs, vq, g2, tid, ks);
                if (ks < 3) loadV2q(vq, xb, n_base, i + 1, tid, ks + 1);
            }
        }

        // A[i+1] committed two iterations' worth of groups ago -> wait is ~free
        asm volatile("cp.async.wait_group 1;" ::: "memory");
        __syncthreads();    // B[nxt] + A[i+1] visible; A[cur]/B[cur] free

        ai = (ai == 2) ? 0 : ai + 1;
        ap = (ap == 2) ? 0 : ap + 1;
    }

    // ---- epilogue ----
    float* bst = (float*)(smem + OFF_ST);
    bst[tid] = 0.f;
    __syncthreads();

    float s4[4] = {0.f, 0.f, 0.f, 0.f}, q4[4] = {0.f, 0.f, 0.f, 0.f};
#pragma unroll
    for (int mt = 0; mt < 2; mt++) {
        const int r0v = wm * 32 + mt * 16 + g;
        const int r1v = r0v + 8;
        const float b0v = bias[o_base + r0v];
        const float b1v = bias[o_base + r1v];
        float* p0 = out + ((size_t)b * COUT + o_base + r0v) * NP + n_base + wn * 64 + 2 * tg;
        float* p1 = out + ((size_t)b * COUT + o_base + r1v) * NP + n_base + wn * 64 + 2 * tg;
#pragma unroll
        for (int nt = 0; nt < 8; nt++) {
            float v0 = acc[mt][nt][0] + b0v;
            float v1 = acc[mt][nt][1] + b0v;
            float v2 = acc[mt][nt][2] + b1v;
            float v3 = acc[mt][nt][3] + b1v;
            *(float2*)(p0 + nt * 8) = make_float2(v0, v1);
            *(float2*)(p1 + nt * 8) = make_float2(v2, v3);
            s4[mt * 2 + 0] += v0 + v1;  q4[mt * 2 + 0] += v0 * v0 + v1 * v1;
            s4[mt * 2 + 1] += v2 + v3;  q4[mt * 2 + 1] += v2 * v2 + v3 * v3;
        }
    }
#pragma unroll
    for (int r = 0; r < 4; r++) {
        float s = s4[r], q = q4[r];
        s += __shfl_xor_sync(0xffffffffu, s, 1);
        s += __shfl_xor_sync(0xffffffffu, s, 2);
        q += __shfl_xor_sync(0xffffffffu, q, 1);
        q += __shfl_xor_sync(0xffffffffu, q, 2);
        if (tg == 0) {
            int lr = wm * 32 + (r >> 1) * 16 + (r & 1) * 8 + g;
            atomicAdd(&bst[lr], s);
            atomicAdd(&bst[128 + lr], q);
        }
    }
    __syncthreads();
    if (tid < 128) {
        atomicAdd(&g_sum[o_base + tid],   bst[tid]);
        atomicAdd(&g_sumsq[o_base + tid], bst[128 + tid]);
    }
}

// ---------------- kernel 3: finalize BN stats ----------------
__global__ void stats_kernel(const float* __restrict__ gamma,
                             const float* __restrict__ beta) {
    int c = threadIdx.x;
    const float inv_n = 1.0f / (float)(BB * NP);
    float mean = g_sum[c] * inv_n;
    float var  = g_sumsq[c] * inv_n - mean * mean;
    float inv  = 1.0f / sqrtf(var + 1e-5f);
    float sc   = gamma[c] * inv;
    g_scale[c] = sc;
    g_shift[c] = beta[c] - mean * sc;
}

// ---------------- kernel 4: apply BN + ReLU ----------------
__global__ void apply_kernel(float* __restrict__ out) {
    size_t i4 = (size_t)blockIdx.x * blockDim.x + threadIdx.x;
    float4 v = ((float4*)out)[i4];
    int o = (int)((i4 * 4) >> 13) & (COUT - 1);
    float s = g_scale[o], t = g_shift[o];
    v.x = fmaxf(v.x * s + t, 0.f);
    v.y = fmaxf(v.y * s + t, 0.f);
    v.z = fmaxf(v.z * s + t, 0.f);
    v.w = fmaxf(v.w * s + t, 0.f);
    ((float4*)out)[i4] = v;
}

// ---------------- launch ----------------
extern "C" void kernel_launch(void* const* d_in, const int* in_sizes, int n_in,
                              void* d_out, int out_size) {
    const float* x      = (const float*)d_in[0];
    const float* coords = (const float*)d_in[1];
    const float* rot    = (const float*)d_in[2];
    const float* dist   = (const float*)d_in[3];
    const float* W      = (const float*)d_in[4];
    const float* bias   = (const float*)d_in[5];
    const float* gamma  = (const float*)d_in[6];
    const float* beta   = (const float*)d_in[7];
    float* out = (float*)d_out;

    cudaFuncSetAttribute(conv15_kernel, cudaFuncAttributeMaxDynamicSharedMemorySize, SMEM_TOTAL);

    prep_kernel<<<1 + 256 + 2304, 256>>>(coords, rot, dist, W);
    conv15_kernel<<<dim3(NP / 128, COUT / 128, BB), 256, SMEM_TOTAL>>>(x, bias, out);
    stats_kernel<<<1, 256>>>(gamma, beta);
    apply_kernel<<<(BB * COUT * NP / 4) / 256, 256>>>(out);
}